// round 11
// baseline (speedup 1.0000x reference)
#include <cuda_runtime.h>
#include <cuda_fp16.h>
#include <cstdint>

#define NT   224
#define KC   32
#define WSZ  14336                 // 224 rows x 64B, one W chunk tile
#define TSZ  4096                  // 64 rows x 64B, one T chunk tile

// smem byte map
#define OFF_V  0                   // v: 2560 f32 (stride 64)        = 10240
#define OFF_H  10240               // h: 100 x 72 f32 (padded)       = 28800
#define OFF_W  39040               // 2 x WSZ (128B aligned)
#define OFF_T  (OFF_W + 2*WSZ)     // 67712 (128B aligned)
#define SMEM_BYTES (OFF_T + 2*TSZ) // 75904  (x3 CTA = 227712 <= 228KB/SM)

// Pre-converted W: 300 chunks x 896 uint4 (14336B each): fp16, k-linear rows of 64B,
// 16B-block swizzle: byte_col ^= (row & 6) << 3
__device__ uint4 g_w16[300 * 896];

static __device__ __forceinline__ uint32_t smem_u32(const void* p) {
    uint32_t a;
    asm("{ .reg .u64 t; cvta.to.shared.u64 t, %1; cvt.u32.u64 %0, t; }" : "=r"(a) : "l"(p));
    return a;
}
static __device__ __forceinline__ void sts128(uint32_t a, uint4 v) {
    asm volatile("st.shared.v4.b32 [%0], {%1,%2,%3,%4};"
                 :: "r"(a), "r"(v.x), "r"(v.y), "r"(v.z), "r"(v.w));
}
static __device__ __forceinline__ void ldsm4(uint32_t& r0, uint32_t& r1,
                                             uint32_t& r2, uint32_t& r3, uint32_t a) {
    asm volatile("ldmatrix.sync.aligned.m8n8.x4.shared.b16 {%0,%1,%2,%3}, [%4];"
                 : "=r"(r0), "=r"(r1), "=r"(r2), "=r"(r3) : "r"(a));
}
static __device__ __forceinline__ void cpasync16(uint32_t s, const void* g) {
    asm volatile("cp.async.cg.shared.global [%0], [%1], 16;"
                 :: "r"(s), "l"(__cvta_generic_to_global(g)) : "memory");
}
static __device__ __forceinline__ void mma16816(float* c, uint32_t a0, uint32_t a1,
                                                uint32_t a2, uint32_t a3,
                                                uint32_t b0, uint32_t b1) {
    asm volatile(
        "mma.sync.aligned.m16n8k16.row.col.f32.f16.f16.f32 "
        "{%0,%1,%2,%3}, {%4,%5,%6,%7}, {%8,%9}, {%0,%1,%2,%3};"
        : "+f"(c[0]), "+f"(c[1]), "+f"(c[2]), "+f"(c[3])
        : "r"(a0), "r"(a1), "r"(a2), "r"(a3), "r"(b0), "r"(b1));
}
static __device__ __forceinline__ uint32_t h2u(__half2 h) {
    return *reinterpret_cast<uint32_t*>(&h);
}

// ---- prep: W fp32 -> fp16, k-linear 64B rows, 16B-block swizzle ----
__global__ void _CIN_prep_kernel(const float* __restrict__ w1,
                                 const float* __restrict__ w2,
                                 const float* __restrict__ w3) {
    int kcg = blockIdx.x;          // global chunk 0..299
    const float* W; int K, kc;
    if (kcg < 50)       { W = w1; K = 1600; kc = kcg; }
    else if (kcg < 175) { W = w2; K = 4000; kc = kcg - 50; }
    else                { W = w3; K = 4000; kc = kcg - 175; }
    const int kbase = kc * KC;
    char* dst = reinterpret_cast<char*>(g_w16 + kcg * 896);
    for (int q = threadIdx.x; q < 896; q += 256) {   // 224 rows x 4 16B-quads
        int row = q >> 2, qq = q & 3;                // quad qq = k-local 8qq..8qq+7
        uint4 val = make_uint4(0, 0, 0, 0);
        if (row < 200) {
            const float* s = W + row*K + kbase + qq*8;
            val.x = h2u(__floats2half2_rn(s[0], s[1]));
            val.y = h2u(__floats2half2_rn(s[2], s[3]));
            val.z = h2u(__floats2half2_rn(s[4], s[5]));
            val.w = h2u(__floats2half2_rn(s[6], s[7]));
        }
        uint32_t byte = row*64 + (((uint32_t)(qq*16)) ^ (((uint32_t)(row & 6)) << 3));
        *reinterpret_cast<uint4*>(dst + byte) = val;
    }
}

// ---- T chunk build: T[d][k] fp16, k-linear 64B rows, same swizzle. tid<128 active ----
template<int Nh, int SRCS>
static __device__ __forceinline__ void build_T(const float* __restrict__ v,
                                               const float* __restrict__ src,
                                               uint32_t tbase, int k0, int tid) {
    if (tid >= 128) return;
    const int d = tid & 63, kq = tid >> 6;
    int cb = k0 + kq*16;
    int m = cb / Nh;
    int n = cb - m*Nh;
    float vm = v[m*64 + d];
    float p[16];
    #pragma unroll
    for (int i = 0; i < 16; i++) {
        if (n == Nh) { n = 0; m++; vm = v[m*64 + d]; }
        p[i] = vm * src[n*SRCS + d];
        n++;
    }
    uint4 q0, q1;   // linear: k 0..7 | 8..15 of this kq half
    q0.x = h2u(__floats2half2_rn(p[0],  p[1]));
    q0.y = h2u(__floats2half2_rn(p[2],  p[3]));
    q0.z = h2u(__floats2half2_rn(p[4],  p[5]));
    q0.w = h2u(__floats2half2_rn(p[6],  p[7]));
    q1.x = h2u(__floats2half2_rn(p[8],  p[9]));
    q1.y = h2u(__floats2half2_rn(p[10], p[11]));
    q1.z = h2u(__floats2half2_rn(p[12], p[13]));
    q1.w = h2u(__floats2half2_rn(p[14], p[15]));
    const uint32_t sw = ((uint32_t)(d & 6)) << 3;
    const uint32_t base = tbase + d*64;
    sts128(base + (((uint32_t)(kq*32     )) ^ sw), q0);
    sts128(base + (((uint32_t)(kq*32 + 16)) ^ sw), q1);
}

// ---- one layer ----
template<int K, int Nh, int SRCS, int CHUNK0, int OUT_OFF, bool LAST>
static __device__ __forceinline__ void layer_run(
    const float* __restrict__ bg, char* smem, uint32_t smem_base,
    float* __restrict__ out, int b, int tid)
{
    const float* v   = reinterpret_cast<const float*>(smem + OFF_V);
    const float* src = (Nh == 40) ? v : reinterpret_cast<const float*>(smem + OFF_H);
    float* h = reinterpret_cast<float*>(smem + OFF_H);
    constexpr int NCH = K / KC;

    const int lane = tid & 31, w = tid >> 5;
    const int g = lane >> 2, tig = lane & 3;
    const int o0 = w * 32;

    // ldmatrix lane decomposition: tile lt = lane>>3, row-in-tile lr = lane&7
    const int lt = lane >> 3, lr = lane & 7;
    const uint32_t lsw = ((uint32_t)(lr & 6)) << 3;
    const uint32_t aRow = (uint32_t)(o0 + (lt & 1)*8 + lr) * 64;
    const uint32_t aColH = (uint32_t)(lt >> 1) * 16;
    const uint32_t bRow = (uint32_t)((lt >> 1)*8 + lr) * 64;
    const uint32_t bColH = (uint32_t)(lt & 1) * 16;

    float c[2][8][4];
    #pragma unroll
    for (int ot = 0; ot < 2; ot++)
        #pragma unroll
        for (int j = 0; j < 8; j++)
            #pragma unroll
            for (int r = 0; r < 4; r++) c[ot][j][r] = 0.0f;

    // stage chunk 0
    {
        const char* gsrc = reinterpret_cast<const char*>(g_w16 + (size_t)CHUNK0 * 896);
        #pragma unroll
        for (int j = 0; j < 4; j++)
            cpasync16(smem_base + OFF_W + (tid + j*NT)*16, gsrc + (tid + j*NT)*16);
        asm volatile("cp.async.commit_group;" ::: "memory");
        build_T<Nh, SRCS>(v, src, smem_base + OFF_T, 0, tid);
        asm volatile("cp.async.wait_group 0;" ::: "memory");
    }
    __syncthreads();

    for (int kc = 0; kc < NCH; kc++) {
        const int cur = kc & 1, nxt = cur ^ 1;
        const bool more = (kc + 1) < NCH;

        // producers first: async W stage + T build for next chunk (overlaps MMA issue)
        if (more) {
            const char* gsrc = reinterpret_cast<const char*>(
                g_w16 + (size_t)(CHUNK0 + kc + 1) * 896);
            uint32_t sdst = smem_base + OFF_W + nxt*WSZ;
            #pragma unroll
            for (int j = 0; j < 4; j++)
                cpasync16(sdst + (tid + j*NT)*16, gsrc + (tid + j*NT)*16);
            asm volatile("cp.async.commit_group;" ::: "memory");
            build_T<Nh, SRCS>(v, src, smem_base + OFF_T + nxt*TSZ, (kc + 1)*KC, tid);
        }

        // MMA on current buffers; register-lean: B frags consumed immediately
        const uint32_t Wb = smem_base + OFF_W + cur*WSZ + aRow;
        const uint32_t Tb = smem_base + OFF_T + cur*TSZ + bRow;
        #pragma unroll
        for (int kq = 0; kq < 2; kq++) {
            const uint32_t aCol = (((uint32_t)(kq*32) + aColH) ^ lsw);
            uint32_t a[2][4];
            #pragma unroll
            for (int ot = 0; ot < 2; ot++)
                ldsm4(a[ot][0], a[ot][1], a[ot][2], a[ot][3],
                      Wb + (uint32_t)ot*1024 + aCol);
            const uint32_t bCol = (((uint32_t)(kq*32) + bColH) ^ lsw);
            #pragma unroll
            for (int jj = 0; jj < 4; jj++) {
                uint32_t b0, b1, b2, b3;
                ldsm4(b0, b1, b2, b3, Tb + (uint32_t)jj*1024 + bCol);
                mma16816(c[0][2*jj],   a[0][0], a[0][1], a[0][2], a[0][3], b0, b1);
                mma16816(c[0][2*jj+1], a[0][0], a[0][1], a[0][2], a[0][3], b2, b3);
                mma16816(c[1][2*jj],   a[1][0], a[1][1], a[1][2], a[1][3], b0, b1);
                mma16816(c[1][2*jj+1], a[1][0], a[1][1], a[1][2], a[1][3], b2, b3);
            }
        }

        if (more)
            asm volatile("cp.async.wait_group 0;" ::: "memory");
        __syncthreads();
    }

    // epilogue
    #pragma unroll
    for (int ot = 0; ot < 2; ot++) {
        const int r0 = o0 + ot*16 + g, r1 = r0 + 8;
        const float bz0 = (r0 < 200) ? bg[r0] : 0.0f;
        const float bz1 = (r1 < 200) ? bg[r1] : 0.0f;
        float s0 = 0.0f, s1 = 0.0f;
        #pragma unroll
        for (int j = 0; j < 8; j++) {
            float y00 = fmaxf(c[ot][j][0] + bz0, 0.0f);
            float y01 = fmaxf(c[ot][j][1] + bz0, 0.0f);
            float y10 = fmaxf(c[ot][j][2] + bz1, 0.0f);
            float y11 = fmaxf(c[ot][j][3] + bz1, 0.0f);
            if (!LAST) {
                const int d = j*8 + 2*tig;
                if (r0 < 100) *reinterpret_cast<float2*>(h + r0*72 + d) = make_float2(y00, y01);
                if (r1 < 100) *reinterpret_cast<float2*>(h + r1*72 + d) = make_float2(y10, y11);
            }
            s0 += y00 + y01;
            s1 += y10 + y11;
        }
        s0 += __shfl_xor_sync(0xFFFFFFFFu, s0, 1);
        s0 += __shfl_xor_sync(0xFFFFFFFFu, s0, 2);
        s1 += __shfl_xor_sync(0xFFFFFFFFu, s1, 1);
        s1 += __shfl_xor_sync(0xFFFFFFFFu, s1, 2);
        if (tig == 0) {
            if (LAST) {
                if (r0 < 200) out[b*400 + 200 + r0] = s0;
                if (r1 < 200) out[b*400 + 200 + r1] = s1;
            } else {
                if (r0 >= 100 && r0 < 200) out[b*400 + OUT_OFF + (r0 - 100)] = s0;
                if (r1 >= 100 && r1 < 200) out[b*400 + OUT_OFF + (r1 - 100)] = s1;
            }
        }
    }
    __syncthreads();   // h fully written before next layer's build_T reads it
}

__global__ void __launch_bounds__(NT, 3)
_CIN_41575283425691_kernel(const float* __restrict__ x,
                           const float* __restrict__ b1,
                           const float* __restrict__ b2,
                           const float* __restrict__ b3,
                           float* __restrict__ out)
{
    extern __shared__ char smem[];
    const uint32_t smem_base = smem_u32(smem);
    const int tid = threadIdx.x;
    const int b   = blockIdx.x;

    float* v = reinterpret_cast<float*>(smem + OFF_V);
    const float* xb = x + b*2560;
    for (int i = tid; i < 2560; i += NT) v[i] = xb[i];
    __syncthreads();

    layer_run<1600,  40, 64,   0,   0, false>(b1, smem, smem_base, out, b, tid);
    layer_run<4000, 100, 72,  50, 100, false>(b2, smem, smem_base, out, b, tid);
    layer_run<4000, 100, 72, 175,   0, true >(b3, smem, smem_base, out, b, tid);
}

extern "C" void kernel_launch(void* const* d_in, const int* in_sizes, int n_in,
                              void* d_out, int out_size)
{
    const float* x  = (const float*)d_in[0];
    const float* w1 = (const float*)d_in[1];
    const float* b1 = (const float*)d_in[2];
    const float* w2 = (const float*)d_in[3];
    const float* b2 = (const float*)d_in[4];
    const float* w3 = (const float*)d_in[5];
    const float* b3 = (const float*)d_in[6];
    float* out = (float*)d_out;

    _CIN_prep_kernel<<<300, 256>>>(w1, w2, w3);

    cudaFuncSetAttribute(_CIN_41575283425691_kernel,
                         cudaFuncAttributeMaxDynamicSharedMemorySize, SMEM_BYTES);
    _CIN_41575283425691_kernel<<<512, NT, SMEM_BYTES>>>(x, b1, b2, b3, out);
}

// round 12
// speedup vs baseline: 1.8133x; 1.8133x over previous
#include <cuda_runtime.h>
#include <cuda_fp16.h>
#include <cstdint>

#define NT   416                   // 13 warps x 16 o-rows = 208
#define SKC  64                    // superchunk k extent
#define WSZ  26624                 // 208 rows x 128B, one W superchunk tile
#define TSZ  8192                  // 64 rows x 128B, one T superchunk tile

// smem byte map
#define OFF_V  0                   // v: 2560 f32 (stride 64)        = 10240
#define OFF_H  10240               // h: 100 x 72 f32 (padded)       = 28800
#define OFF_W  39040               // 2 x WSZ (128B aligned)
#define OFF_T  (OFF_W + 2*WSZ)     // 92288 (128B aligned)
#define SMEM_BYTES (OFF_T + 2*TSZ) // 108672  (x2 CTA = 217344 <= 228KB)

// Pre-converted W: 151 superchunks x 1664 uint4 (26624B each): fp16, k-linear 128B rows,
// full swizzle: byte_col16 ^= (row & 7) << 4 ; k-tail beyond K zero-padded.
__device__ uint4 g_w16[151 * 1664];

static __device__ __forceinline__ uint32_t smem_u32(const void* p) {
    uint32_t a;
    asm("{ .reg .u64 t; cvta.to.shared.u64 t, %1; cvt.u32.u64 %0, t; }" : "=r"(a) : "l"(p));
    return a;
}
static __device__ __forceinline__ void sts128(uint32_t a, uint4 v) {
    asm volatile("st.shared.v4.b32 [%0], {%1,%2,%3,%4};"
                 :: "r"(a), "r"(v.x), "r"(v.y), "r"(v.z), "r"(v.w));
}
static __device__ __forceinline__ void ldsm4(uint32_t& r0, uint32_t& r1,
                                             uint32_t& r2, uint32_t& r3, uint32_t a) {
    asm volatile("ldmatrix.sync.aligned.m8n8.x4.shared.b16 {%0,%1,%2,%3}, [%4];"
                 : "=r"(r0), "=r"(r1), "=r"(r2), "=r"(r3) : "r"(a));
}
static __device__ __forceinline__ void cpasync16(uint32_t s, const void* g) {
    asm volatile("cp.async.cg.shared.global [%0], [%1], 16;"
                 :: "r"(s), "l"(__cvta_generic_to_global(g)) : "memory");
}
static __device__ __forceinline__ void mma16816(float* c, uint32_t a0, uint32_t a1,
                                                uint32_t a2, uint32_t a3,
                                                uint32_t b0, uint32_t b1) {
    asm volatile(
        "mma.sync.aligned.m16n8k16.row.col.f32.f16.f16.f32 "
        "{%0,%1,%2,%3}, {%4,%5,%6,%7}, {%8,%9}, {%0,%1,%2,%3};"
        : "+f"(c[0]), "+f"(c[1]), "+f"(c[2]), "+f"(c[3])
        : "r"(a0), "r"(a1), "r"(a2), "r"(a3), "r"(b0), "r"(b1));
}
static __device__ __forceinline__ uint32_t h2u(__half2 h) {
    return *reinterpret_cast<uint32_t*>(&h);
}

// ---- prep: W fp32 -> fp16 superchunk tiles, 208x128B rows, full swizzle, zero-pad ----
__global__ void _CIN_prep_kernel(const float* __restrict__ w1,
                                 const float* __restrict__ w2,
                                 const float* __restrict__ w3) {
    int sc = blockIdx.x;           // global superchunk 0..150
    const float* W; int K, scl;
    if (sc < 25)      { W = w1; K = 1600; scl = sc; }
    else if (sc < 88) { W = w2; K = 4000; scl = sc - 25; }
    else              { W = w3; K = 4000; scl = sc - 88; }
    const int kbase = scl * SKC;
    char* dst = reinterpret_cast<char*>(g_w16 + (size_t)sc * 1664);
    for (int q = threadIdx.x; q < 1664; q += 256) {   // 208 rows x 8 16B-quads
        int row = q >> 3, qq = q & 7;                 // quad qq = k-local 8qq..8qq+7
        int k = kbase + qq*8;
        uint4 val = make_uint4(0, 0, 0, 0);
        if (row < 200 && k < K) {
            const float* s = W + row*K + k;
            val.x = h2u(__floats2half2_rn(s[0], s[1]));
            val.y = h2u(__floats2half2_rn(s[2], s[3]));
            val.z = h2u(__floats2half2_rn(s[4], s[5]));
            val.w = h2u(__floats2half2_rn(s[6], s[7]));
        }
        uint32_t byte = row*128 + (((uint32_t)(qq*16)) ^ (((uint32_t)(row & 7)) << 4));
        *reinterpret_cast<uint4*>(dst + byte) = val;
    }
}

// ---- T superchunk build: 512 tasks of (d, 8k); low register footprint ----
template<int K, int Nh, int SRCS>
static __device__ __forceinline__ void build_T(const float* __restrict__ v,
                                               const float* __restrict__ src,
                                               uint32_t tbase, int k0, int tid) {
    for (int i = tid; i < 512; i += NT) {     // task = (d, q8)
        const int d = i & 63, q8 = i >> 6;
        const int kb = k0 + q8*8;
        if (kb >= K) continue;                // zero-padded W covers the tail
        int m = kb / Nh;
        int n = kb - m*Nh;
        float vm = v[m*64 + d];
        float p[8];
        #pragma unroll
        for (int t = 0; t < 8; t++) {
            if (n == Nh) { n = 0; m++; vm = v[m*64 + d]; }
            p[t] = vm * src[n*SRCS + d];
            n++;
        }
        uint4 q;
        q.x = h2u(__floats2half2_rn(p[0], p[1]));
        q.y = h2u(__floats2half2_rn(p[2], p[3]));
        q.z = h2u(__floats2half2_rn(p[4], p[5]));
        q.w = h2u(__floats2half2_rn(p[6], p[7]));
        const uint32_t sw = ((uint32_t)(d & 7)) << 4;
        sts128(tbase + d*128 + (((uint32_t)(q8*16)) ^ sw), q);
    }
}

// ---- one layer ----
template<int K, int Nh, int SRCS, int SC0, int NSC, int OUT_OFF, bool LAST>
static __device__ __forceinline__ void layer_run(
    const float* __restrict__ bg, char* smem, uint32_t smem_base,
    float* __restrict__ out, int b, int tid)
{
    const float* v   = reinterpret_cast<const float*>(smem + OFF_V);
    const float* src = (Nh == 40) ? v : reinterpret_cast<const float*>(smem + OFF_H);
    float* h = reinterpret_cast<float*>(smem + OFF_H);

    const int lane = tid & 31, w = tid >> 5;
    const int g = lane >> 2, tig = lane & 3;
    const int o0 = w * 16;

    // ldmatrix lane decomposition
    const int lt = lane >> 3, lr = lane & 7;
    const uint32_t lsw = ((uint32_t)lr) << 4;
    const uint32_t aRowB = (uint32_t)(o0 + (lt & 1)*8 + lr) * 128;
    const uint32_t aColH = (uint32_t)(lt >> 1) * 16;
    const uint32_t bRowB = (uint32_t)((lt >> 1)*8 + lr) * 128;
    const uint32_t bColH = (uint32_t)(lt & 1) * 16;

    float c[8][4];   // 32 accumulator regs: 8 d-tiles x (2 o-rows x 2 d)
    #pragma unroll
    for (int j = 0; j < 8; j++)
        #pragma unroll
        for (int r = 0; r < 4; r++) c[j][r] = 0.0f;

    // stage superchunk 0
    {
        const char* gsrc = reinterpret_cast<const char*>(g_w16 + (size_t)SC0 * 1664);
        #pragma unroll
        for (int j = 0; j < 4; j++)
            cpasync16(smem_base + OFF_W + (tid + j*NT)*16, gsrc + (tid + j*NT)*16);
        asm volatile("cp.async.commit_group;" ::: "memory");
        build_T<K, Nh, SRCS>(v, src, smem_base + OFF_T, 0, tid);
        asm volatile("cp.async.wait_group 0;" ::: "memory");
    }
    __syncthreads();

    for (int sc = 0; sc < NSC; sc++) {
        const int cur = sc & 1, nxt = cur ^ 1;
        const bool more = (sc + 1) < NSC;

        // producers first: async W stage + T build for next superchunk
        if (more) {
            const char* gsrc = reinterpret_cast<const char*>(
                g_w16 + (size_t)(SC0 + sc + 1) * 1664);
            uint32_t sdst = smem_base + OFF_W + nxt*WSZ;
            #pragma unroll
            for (int j = 0; j < 4; j++)
                cpasync16(sdst + (tid + j*NT)*16, gsrc + (tid + j*NT)*16);
            asm volatile("cp.async.commit_group;" ::: "memory");
            build_T<K, Nh, SRCS>(v, src, smem_base + OFF_T + nxt*TSZ, (sc + 1)*SKC, tid);
        }

        // MMA: 4 kq x (1 A-ldsm + 4 B-ldsm + 8 MMA), B consumed immediately
        const uint32_t Wb = smem_base + OFF_W + cur*WSZ + aRowB;
        const uint32_t Tb = smem_base + OFF_T + cur*TSZ + bRowB;
        #pragma unroll
        for (int kq = 0; kq < 4; kq++) {
            uint32_t a0, a1, a2, a3;
            ldsm4(a0, a1, a2, a3, Wb + (((uint32_t)(kq*32) + aColH) ^ lsw));
            const uint32_t bCol = (((uint32_t)(kq*32) + bColH) ^ lsw);
            #pragma unroll
            for (int jj = 0; jj < 4; jj++) {
                uint32_t b0, b1, b2, b3;
                ldsm4(b0, b1, b2, b3, Tb + (uint32_t)jj*2048 + bCol);
                mma16816(c[2*jj],   a0, a1, a2, a3, b0, b1);
                mma16816(c[2*jj+1], a0, a1, a2, a3, b2, b3);
            }
        }

        if (more)
            asm volatile("cp.async.wait_group 0;" ::: "memory");
        __syncthreads();
    }

    // epilogue
    {
        const int r0 = o0 + g, r1 = r0 + 8;
        const float bz0 = (r0 < 200) ? bg[r0] : 0.0f;
        const float bz1 = (r1 < 200) ? bg[r1] : 0.0f;
        float s0 = 0.0f, s1 = 0.0f;
        #pragma unroll
        for (int j = 0; j < 8; j++) {
            float y00 = fmaxf(c[j][0] + bz0, 0.0f);
            float y01 = fmaxf(c[j][1] + bz0, 0.0f);
            float y10 = fmaxf(c[j][2] + bz1, 0.0f);
            float y11 = fmaxf(c[j][3] + bz1, 0.0f);
            if (!LAST) {
                const int d = j*8 + 2*tig;
                if (r0 < 100) *reinterpret_cast<float2*>(h + r0*72 + d) = make_float2(y00, y01);
                if (r1 < 100) *reinterpret_cast<float2*>(h + r1*72 + d) = make_float2(y10, y11);
            }
            s0 += y00 + y01;
            s1 += y10 + y11;
        }
        s0 += __shfl_xor_sync(0xFFFFFFFFu, s0, 1);
        s0 += __shfl_xor_sync(0xFFFFFFFFu, s0, 2);
        s1 += __shfl_xor_sync(0xFFFFFFFFu, s1, 1);
        s1 += __shfl_xor_sync(0xFFFFFFFFu, s1, 2);
        if (tig == 0) {
            if (LAST) {
                if (r0 < 200) out[b*400 + 200 + r0] = s0;
                if (r1 < 200) out[b*400 + 200 + r1] = s1;
            } else {
                if (r0 >= 100 && r0 < 200) out[b*400 + OUT_OFF + (r0 - 100)] = s0;
                if (r1 >= 100 && r1 < 200) out[b*400 + OUT_OFF + (r1 - 100)] = s1;
            }
        }
    }
    __syncthreads();   // h fully written before next layer's build_T reads it
}

__global__ void __launch_bounds__(NT, 2)
_CIN_41575283425691_kernel(const float* __restrict__ x,
                           const float* __restrict__ b1,
                           const float* __restrict__ b2,
                           const float* __restrict__ b3,
                           float* __restrict__ out)
{
    extern __shared__ char smem[];
    const uint32_t smem_base = smem_u32(smem);
    const int tid = threadIdx.x;
    const int b   = blockIdx.x;

    float* v = reinterpret_cast<float*>(smem + OFF_V);
    const float* xb = x + b*2560;
    for (int i = tid; i < 2560; i += NT) v[i] = xb[i];
    __syncthreads();

    layer_run<1600,  40, 64,  0, 25,   0, false>(b1, smem, smem_base, out, b, tid);
    layer_run<4000, 100, 72, 25, 63, 100, false>(b2, smem, smem_base, out, b, tid);
    layer_run<4000, 100, 72, 88, 63,   0, true >(b3, smem, smem_base, out, b, tid);
}

extern "C" void kernel_launch(void* const* d_in, const int* in_sizes, int n_in,
                              void* d_out, int out_size)
{
    const float* x  = (const float*)d_in[0];
    const float* w1 = (const float*)d_in[1];
    const float* b1 = (const float*)d_in[2];
    const float* w2 = (const float*)d_in[3];
    const float* b2 = (const float*)d_in[4];
    const float* w3 = (const float*)d_in[5];
    const float* b3 = (const float*)d_in[6];
    float* out = (float*)d_out;

    _CIN_prep_kernel<<<151, 256>>>(w1, w2, w3);

    cudaFuncSetAttribute(_CIN_41575283425691_kernel,
                         cudaFuncAttributeMaxDynamicSharedMemorySize, SMEM_BYTES);
    _CIN_41575283425691_kernel<<<512, NT, SMEM_BYTES>>>(x, b1, b2, b3, out);
}

// round 13
// speedup vs baseline: 1.9728x; 1.0879x over previous
#include <cuda_runtime.h>
#include <cuda_fp16.h>
#include <cstdint>

#define NT   416                   // 13 warps x 16 o-rows = 208
#define SKC  64                    // superchunk k extent
#define TSZ  8192                  // 64 rows x 128B, one T superchunk tile

// smem byte map
#define OFF_V  0                   // v: 2560 f32 (stride 64)        = 10240
#define OFF_H  10240               // h: 100 x 72 f32 (padded)       = 28800
#define OFF_T  39040               // 2 x TSZ (128B aligned)
#define SMEM_BYTES (OFF_T + 2*TSZ) // 55424  (x2 CTA = 110848)

// Pre-arranged W in A-fragment order:
// g_wf[sc][otile 0..12][kq 0..3][lane 0..31] = uint4{a0,a1,a2,a3} for that lane.
// a0=W[o0+g][k,k+1] a1=W[o0+g+8][k,k+1] a2=W[o0+g][k+8,k+9] a3=W[o0+g+8][k+8,k+9],
// o0=otile*16, g=lane>>2, k=sc*64+kq*16+2*(lane&3). Out-of-range rows/k are zero.
__device__ uint4 g_wf[151 * 1664];

static __device__ __forceinline__ uint32_t smem_u32(const void* p) {
    uint32_t a;
    asm("{ .reg .u64 t; cvta.to.shared.u64 t, %1; cvt.u32.u64 %0, t; }" : "=r"(a) : "l"(p));
    return a;
}
static __device__ __forceinline__ void sts128(uint32_t a, uint4 v) {
    asm volatile("st.shared.v4.b32 [%0], {%1,%2,%3,%4};"
                 :: "r"(a), "r"(v.x), "r"(v.y), "r"(v.z), "r"(v.w));
}
static __device__ __forceinline__ void ldsm4(uint32_t& r0, uint32_t& r1,
                                             uint32_t& r2, uint32_t& r3, uint32_t a) {
    asm volatile("ldmatrix.sync.aligned.m8n8.x4.shared.b16 {%0,%1,%2,%3}, [%4];"
                 : "=r"(r0), "=r"(r1), "=r"(r2), "=r"(r3) : "r"(a));
}
static __device__ __forceinline__ void mma16816(float* c, uint32_t a0, uint32_t a1,
                                                uint32_t a2, uint32_t a3,
                                                uint32_t b0, uint32_t b1) {
    asm volatile(
        "mma.sync.aligned.m16n8k16.row.col.f32.f16.f16.f32 "
        "{%0,%1,%2,%3}, {%4,%5,%6,%7}, {%8,%9}, {%0,%1,%2,%3};"
        : "+f"(c[0]), "+f"(c[1]), "+f"(c[2]), "+f"(c[3])
        : "r"(a0), "r"(a1), "r"(a2), "r"(a3), "r"(b0), "r"(b1));
}
static __device__ __forceinline__ uint32_t h2u(__half2 h) {
    return *reinterpret_cast<uint32_t*>(&h);
}

// ---- prep: W fp32 -> fp16 A-fragment-ordered global tiles, zero-padded ----
__global__ void _CIN_prep_kernel(const float* __restrict__ w1,
                                 const float* __restrict__ w2,
                                 const float* __restrict__ w3) {
    int sc = blockIdx.x;           // global superchunk 0..150
    const float* W; int K, scl;
    if (sc < 25)      { W = w1; K = 1600; scl = sc; }
    else if (sc < 88) { W = w2; K = 4000; scl = sc - 25; }
    else              { W = w3; K = 4000; scl = sc - 88; }
    const int kbase = scl * SKC;
    uint4* dst = g_wf + (size_t)sc * 1664;
    for (int idx = threadIdx.x; idx < 1664; idx += 256) {  // 13 ot x 4 kq x 32 lanes
        const int lane = idx & 31, kq = (idx >> 5) & 3, ot = idx >> 7;
        const int g = lane >> 2, tig = lane & 3;
        const int r0 = ot*16 + g, r1 = r0 + 8;
        const int k = kbase + kq*16 + 2*tig;
        uint4 val = make_uint4(0, 0, 0, 0);
        if (k < K) {
            if (r0 < 200) {
                const float* s = W + r0*K + k;
                val.x = h2u(__floats2half2_rn(s[0], s[1]));
                val.z = h2u(__floats2half2_rn(s[8], s[9]));
            }
            if (r1 < 200) {
                const float* s = W + r1*K + k;
                val.y = h2u(__floats2half2_rn(s[0], s[1]));
                val.w = h2u(__floats2half2_rn(s[8], s[9]));
            }
        }
        dst[idx] = val;
    }
}

// ---- T superchunk build: 512 tasks of (d, 8k); low register footprint ----
template<int K, int Nh, int SRCS>
static __device__ __forceinline__ void build_T(const float* __restrict__ v,
                                               const float* __restrict__ src,
                                               uint32_t tbase, int k0, int tid) {
    for (int i = tid; i < 512; i += NT) {     // task = (d, q8)
        const int d = i & 63, q8 = i >> 6;
        const int kb = k0 + q8*8;
        if (kb >= K) continue;                // zero-padded W covers the tail
        int m = kb / Nh;
        int n = kb - m*Nh;
        float vm = v[m*64 + d];
        float p[8];
        #pragma unroll
        for (int t = 0; t < 8; t++) {
            if (n == Nh) { n = 0; m++; vm = v[m*64 + d]; }
            p[t] = vm * src[n*SRCS + d];
            n++;
        }
        uint4 q;
        q.x = h2u(__floats2half2_rn(p[0], p[1]));
        q.y = h2u(__floats2half2_rn(p[2], p[3]));
        q.z = h2u(__floats2half2_rn(p[4], p[5]));
        q.w = h2u(__floats2half2_rn(p[6], p[7]));
        const uint32_t sw = ((uint32_t)(d & 7)) << 4;
        sts128(tbase + d*128 + (((uint32_t)(q8*16)) ^ sw), q);
    }
}

// ---- one layer ----
template<int K, int Nh, int SRCS, int SC0, int NSC, int OUT_OFF, bool LAST>
static __device__ __forceinline__ void layer_run(
    const float* __restrict__ bg, char* smem, uint32_t smem_base,
    float* __restrict__ out, int b, int tid)
{
    const float* v   = reinterpret_cast<const float*>(smem + OFF_V);
    const float* src = (Nh == 40) ? v : reinterpret_cast<const float*>(smem + OFF_H);
    float* h = reinterpret_cast<float*>(smem + OFF_H);

    const int lane = tid & 31, w = tid >> 5;
    const int g = lane >> 2, tig = lane & 3;
    const int o0 = w * 16;

    // ldmatrix lane decomposition (B only)
    const int lt = lane >> 3, lr = lane & 7;
    const uint32_t lsw = ((uint32_t)lr) << 4;
    const uint32_t bRowB = (uint32_t)((lt >> 1)*8 + lr) * 128;
    const uint32_t bColH = (uint32_t)(lt & 1) * 16;

    float c[8][4];   // 32 accumulator regs
    #pragma unroll
    for (int j = 0; j < 8; j++)
        #pragma unroll
        for (int r = 0; r < 4; r++) c[j][r] = 0.0f;

    // stage T superchunk 0
    build_T<K, Nh, SRCS>(v, src, smem_base + OFF_T, 0, tid);
    __syncthreads();

    // per-warp A fragment stream (coalesced LDG.128, L1D-cached, shared by both CTAs)
    const uint4* Aw = g_wf + ((size_t)SC0*13 + (size_t)w)*128 + lane;

    for (int sc = 0; sc < NSC; sc++) {
        const int cur = sc & 1, nxt = cur ^ 1;
        const bool more = (sc + 1) < NSC;

        // producer first: T build for next superchunk (overlaps MMA issue)
        if (more)
            build_T<K, Nh, SRCS>(v, src, smem_base + OFF_T + nxt*TSZ, (sc + 1)*SKC, tid);

        // MMA: 4 kq x (1 LDG.128 A + 4 B-ldsm + 8 MMA)
        const uint32_t Tb = smem_base + OFF_T + cur*TSZ + bRowB;
        const uint4* As = Aw + (size_t)sc*1664;
        #pragma unroll
        for (int kq = 0; kq < 4; kq++) {
            const uint4 a = __ldg(As + kq*32);
            const uint32_t bCol = (((uint32_t)(kq*32) + bColH) ^ lsw);
            #pragma unroll
            for (int jj = 0; jj < 4; jj++) {
                uint32_t b0, b1, b2, b3;
                ldsm4(b0, b1, b2, b3, Tb + (uint32_t)jj*2048 + bCol);
                mma16816(c[2*jj],   a.x, a.y, a.z, a.w, b0, b1);
                mma16816(c[2*jj+1], a.x, a.y, a.z, a.w, b2, b3);
            }
        }
        __syncthreads();
    }

    // epilogue
    {
        const int r0 = o0 + g, r1 = r0 + 8;
        const float bz0 = (r0 < 200) ? bg[r0] : 0.0f;
        const float bz1 = (r1 < 200) ? bg[r1] : 0.0f;
        float s0 = 0.0f, s1 = 0.0f;
        #pragma unroll
        for (int j = 0; j < 8; j++) {
            float y00 = fmaxf(c[j][0] + bz0, 0.0f);
            float y01 = fmaxf(c[j][1] + bz0, 0.0f);
            float y10 = fmaxf(c[j][2] + bz1, 0.0f);
            float y11 = fmaxf(c[j][3] + bz1, 0.0f);
            if (!LAST) {
                const int d = j*8 + 2*tig;
                if (r0 < 100) *reinterpret_cast<float2*>(h + r0*72 + d) = make_float2(y00, y01);
                if (r1 < 100) *reinterpret_cast<float2*>(h + r1*72 + d) = make_float2(y10, y11);
            }
            s0 += y00 + y01;
            s1 += y10 + y11;
        }
        s0 += __shfl_xor_sync(0xFFFFFFFFu, s0, 1);
        s0 += __shfl_xor_sync(0xFFFFFFFFu, s0, 2);
        s1 += __shfl_xor_sync(0xFFFFFFFFu, s1, 1);
        s1 += __shfl_xor_sync(0xFFFFFFFFu, s1, 2);
        if (tig == 0) {
            if (LAST) {
                if (r0 < 200) out[b*400 + 200 + r0] = s0;
                if (r1 < 200) out[b*400 + 200 + r1] = s1;
            } else {
                if (r0 >= 100 && r0 < 200) out[b*400 + OUT_OFF + (r0 - 100)] = s0;
                if (r1 >= 100 && r1 < 200) out[b*400 + OUT_OFF + (r1 - 100)] = s1;
            }
        }
    }
    __syncthreads();   // h fully written before next layer's build_T reads it
}

__global__ void __launch_bounds__(NT, 2)
_CIN_41575283425691_kernel(const float* __restrict__ x,
                           const float* __restrict__ b1,
                           const float* __restrict__ b2,
                           const float* __restrict__ b3,
                           float* __restrict__ out)
{
    extern __shared__ char smem[];
    const uint32_t smem_base = smem_u32(smem);
    const int tid = threadIdx.x;
    const int b   = blockIdx.x;

    float* v = reinterpret_cast<float*>(smem + OFF_V);
    const float* xb = x + b*2560;
    for (int i = tid; i < 2560; i += NT) v[i] = xb[i];
    __syncthreads();

    layer_run<1600,  40, 64,  0, 25,   0, false>(b1, smem, smem_base, out, b, tid);
    layer_run<4000, 100, 72, 25, 63, 100, false>(b2, smem, smem_base, out, b, tid);
    layer_run<4000, 100, 72, 88, 63,   0, true >(b3, smem, smem_base, out, b, tid);
}

extern "C" void kernel_launch(void* const* d_in, const int* in_sizes, int n_in,
                              void* d_out, int out_size)
{
    const float* x  = (const float*)d_in[0];
    const float* w1 = (const float*)d_in[1];
    const float* b1 = (const float*)d_in[2];
    const float* w2 = (const float*)d_in[3];
    const float* b2 = (const float*)d_in[4];
    const float* w3 = (const float*)d_in[5];
    const float* b3 = (const float*)d_in[6];
    float* out = (float*)d_out;

    _CIN_prep_kernel<<<151, 256>>>(w1, w2, w3);

    cudaFuncSetAttribute(_CIN_41575283425691_kernel,
                         cudaFuncAttributeMaxDynamicSharedMemorySize, SMEM_BYTES);
    _CIN_41575283425691_kernel<<<512, NT, SMEM_BYTES>>>(x, b1, b2, b3, out);
}